// round 8
// baseline (speedup 1.0000x reference)
#include <cuda_runtime.h>
#include <cuda_bf16.h>
#include <math.h>
#include <float.h>

#define Bc 4
#define Lc 1024
#define Hc 12
#define Ec 64
#define BM 64
#define BN 64
#define NIT (Lc / BM)    // 16 i-tiles
#define NBH (Bc * Hc)    // 48
#define PBH (Lc * 128)   // 131072 bytes per (b,h) per bf16 array

// ---------------------------------------------------------------------------
// global scratch (allocation-free rule: __device__ globals)
// bf16 hi/lo images, PRE-SWIZZLED exactly like the stage2 smem tiles
// ---------------------------------------------------------------------------
__device__ __align__(16) unsigned char g_qhi[NBH * PBH];
__device__ __align__(16) unsigned char g_qlo[NBH * PBH];
__device__ __align__(16) unsigned char g_khi[NBH * PBH];
__device__ __align__(16) unsigned char g_klo[NBH * PBH];
__device__ __align__(16) unsigned char g_vhi[NBH * PBH];
__device__ __align__(16) unsigned char g_vlo[NBH * PBH];
__device__ float g_wexp[NBH * Lc];
__device__ float g_invz[NBH * Lc];
__device__ float g_kkn[NBH * Lc];          // -km * |k|^2
__device__ float g_gq[NBH * 64 * Ec];      // 16-row sums [bh][g*4+r][e]

// ---------------------------------------------------------------------------
// helpers
// ---------------------------------------------------------------------------
__device__ __forceinline__ unsigned smem_u32(const void* p) {
    unsigned a;
    asm("{ .reg .u64 t; cvta.to.shared.u64 t, %1; cvt.u32.u64 %0, t; }"
        : "=r"(a) : "l"(p));
    return a;
}
__device__ __forceinline__ void cpa16(unsigned dst, const void* src) {
    asm volatile("cp.async.cg.shared.global [%0], [%1], 16;" :: "r"(dst), "l"(src));
}
__device__ __forceinline__ void ldsm4(unsigned* r, unsigned addr) {
    asm volatile("ldmatrix.sync.aligned.m8n8.x4.shared.b16 {%0,%1,%2,%3}, [%4];"
        : "=r"(r[0]), "=r"(r[1]), "=r"(r[2]), "=r"(r[3]) : "r"(addr));
}
__device__ __forceinline__ void ldsm2(unsigned* r, unsigned addr) {
    asm volatile("ldmatrix.sync.aligned.m8n8.x2.shared.b16 {%0,%1}, [%2];"
        : "=r"(r[0]), "=r"(r[1]) : "r"(addr));
}
__device__ __forceinline__ void ldsm2t(unsigned* r, unsigned addr) {
    asm volatile("ldmatrix.sync.aligned.m8n8.x2.trans.shared.b16 {%0,%1}, [%2];"
        : "=r"(r[0]), "=r"(r[1]) : "r"(addr));
}
__device__ __forceinline__ void mma_bf16(float* c, const unsigned* a, const unsigned* b) {
    asm volatile(
        "mma.sync.aligned.m16n8k16.row.col.f32.bf16.bf16.f32 "
        "{%0,%1,%2,%3}, {%4,%5,%6,%7}, {%8,%9}, {%0,%1,%2,%3};"
        : "+f"(c[0]), "+f"(c[1]), "+f"(c[2]), "+f"(c[3])
        : "r"(a[0]), "r"(a[1]), "r"(a[2]), "r"(a[3]), "r"(b[0]), "r"(b[1]));
}
__device__ __forceinline__ void splitpack(float p0, float p1, unsigned& hi, unsigned& lo) {
    __nv_bfloat162 h2 = __floats2bfloat162_rn(p0, p1);
    float r0 = p0 - __low2float(h2);
    float r1 = p1 - __high2float(h2);
    __nv_bfloat162 l2 = __floats2bfloat162_rn(r0, r1);
    hi = *(unsigned*)&h2;
    lo = *(unsigned*)&l2;
}
// swizzled byte offset within a (row, c4) cell; c4 = group of 4 elements
__device__ __forceinline__ unsigned swoff(int row, int c4) {
    return (unsigned)(row * 128 + ((c4 * 8) ^ ((row & 7) << 4)));
}

// stage2 smem: Q hi/lo 2x8K, K double buffers 2x16K, V single 16K, kn 2x256B
#define SQHI 0
#define SQLO 8192
#define SKB  16384            // + buf*16384 ; hi at +0, lo at +8192
#define SVHI 49152
#define SVLO 57344
#define SKNN 65536
#define STOT (65536 + 512)

// ---------------------------------------------------------------------------
// 1) merged: blocks [0,NBH) = score+scan; blocks [NBH, NBH+4*NBH) = prep_kv
// ---------------------------------------------------------------------------
__global__ void __launch_bounds__(1024) prep_kernel(
    const float* __restrict__ q, const float* __restrict__ wv,
    const float* __restrict__ q_mask,
    const float* __restrict__ k, const float* __restrict__ v,
    const float* __restrict__ k_mask)
{
    int tid = threadIdx.x;
    if (blockIdx.x >= NBH) {
        // ---------------- prep_kv part: 256 rows per block ----------------
        int pb = blockIdx.x - NBH;
        int bh = pb >> 2, qtr = pb & 3;
        int b = bh / Hc, h = bh % Hc;
        float km = k_mask[b * Lc];
        unsigned char* khi = g_khi + (size_t)bh * PBH;
        unsigned char* klo = g_klo + (size_t)bh * PBH;
        unsigned char* vhi = g_vhi + (size_t)bh * PBH;
        unsigned char* vlo = g_vlo + (size_t)bh * PBH;
        #pragma unroll
        for (int itr = 0; itr < 4; ++itr) {
            int idx = itr * 1024 + tid;
            int row = qtr * 256 + (idx >> 4), c4 = idx & 15;
            size_t goff = ((size_t)((b * Lc + row) * Hc + h)) * Ec + c4 * 4;
            unsigned off = swoff(row, c4);
            float4 kx = *(const float4*)(k + goff);
            {
                unsigned h0, l0_, h1, l1;
                splitpack(kx.x, kx.y, h0, l0_);
                splitpack(kx.z, kx.w, h1, l1);
                *(uint2*)(khi + off) = make_uint2(h0, h1);
                *(uint2*)(klo + off) = make_uint2(l0_, l1);
            }
            {
                float4 x = *(const float4*)(v + goff);
                unsigned h0, l0_, h1, l1;
                splitpack(x.x, x.y, h0, l0_);
                splitpack(x.z, x.w, h1, l1);
                *(uint2*)(vhi + off) = make_uint2(h0, h1);
                *(uint2*)(vlo + off) = make_uint2(l0_, l1);
            }
            float ps = kx.x * kx.x + kx.y * kx.y + kx.z * kx.z + kx.w * kx.w;
            #pragma unroll
            for (int o = 1; o < 16; o <<= 1) ps += __shfl_xor_sync(0xffffffffu, ps, o);
            if ((tid & 15) == 0) g_kkn[bh * Lc + row] = -km * ps;
        }
        return;
    }

    // ---------------- score + softmax-scan part ----------------
    int bh = blockIdx.x;
    int b = bh / Hc, h = bh % Hc;

    __shared__ float s_sh[Lc];
    __shared__ float w_sh[Ec];
    __shared__ float red[32];
    __shared__ float Msh;

    int lane = tid & 31, warp = tid >> 5;

    if (tid < Ec) w_sh[tid] = wv[h * Ec + tid];
    __syncthreads();
    float qm = q_mask[b * Lc];

    for (int j = warp; j < Lc; j += 32) {
        const float* qrow = q + ((size_t)((b * Lc + j) * Hc + h)) * Ec;
        float p = qrow[lane] * w_sh[lane] + qrow[lane + 32] * w_sh[lane + 32];
        #pragma unroll
        for (int o = 16; o; o >>= 1) p += __shfl_xor_sync(0xffffffffu, p, o);
        if (lane == 0) s_sh[j] = p * qm;
    }
    __syncthreads();

    float m = s_sh[tid];
    #pragma unroll
    for (int o = 16; o; o >>= 1) m = fmaxf(m, __shfl_xor_sync(0xffffffffu, m, o));
    if (lane == 0) red[warp] = m;
    __syncthreads();
    if (warp == 0) {
        float t = red[lane];
        #pragma unroll
        for (int o = 16; o; o >>= 1) t = fmaxf(t, __shfl_xor_sync(0xffffffffu, t, o));
        if (lane == 0) Msh = t;
    }
    __syncthreads();
    float M = Msh;

    float wexp = __expf(s_sh[tid] - M);
    float sc = wexp;
    #pragma unroll
    for (int o = 1; o < 32; o <<= 1) {
        float t = __shfl_up_sync(0xffffffffu, sc, o);
        if (lane >= o) sc += t;
    }
    if (lane == 31) red[warp] = sc;
    __syncthreads();
    if (warp == 0) {
        float v0 = red[lane];
        float scn = v0;
        #pragma unroll
        for (int o = 1; o < 32; o <<= 1) {
            float t = __shfl_up_sync(0xffffffffu, scn, o);
            if (lane >= o) scn += t;
        }
        red[lane] = scn - v0;
    }
    __syncthreads();
    float Z = sc + red[warp];
    g_wexp[bh * Lc + tid] = wexp;
    g_invz[bh * Lc + tid] = 1.0f / Z;
}

// ---------------------------------------------------------------------------
// 2) 16-row sums: g_gq[bh][g*4+r][e]. grid (NBH,16), 256 threads
// ---------------------------------------------------------------------------
__global__ void __launch_bounds__(256) gsum_kernel(const float* __restrict__ q)
{
    int bh = blockIdx.x, g = blockIdx.y;
    int b = bh / Hc, h = bh % Hc;
    int e = threadIdx.x & 63, r = threadIdx.x >> 6;
    int j0 = g * 64 + r * 16;
    float s = 0.f;
    #pragma unroll
    for (int jj = 0; jj < 16; ++jj) {
        int j = j0 + jj;
        s += g_wexp[bh * Lc + j] *
             q[((size_t)((b * Lc + j) * Hc + h)) * Ec + e];
    }
    g_gq[(bh * 64 + g * 4 + r) * Ec + e] = s;
}

// ---------------------------------------------------------------------------
// 3) qhat scan -> smem stage -> vectorized bf16 hi/lo. grid (NBH,16), 256 thr
// ---------------------------------------------------------------------------
__global__ void __launch_bounds__(256) qhat_kernel(const float* __restrict__ q)
{
    __shared__ float sbuf[64][64];
    int bh = blockIdx.x, g = blockIdx.y;
    int b = bh / Hc, h = bh % Hc;
    int e = threadIdx.x & 63, r = threadIdx.x >> 6;
    int gr = g * 4 + r;
    unsigned char* qhi = g_qhi + (size_t)bh * PBH;
    unsigned char* qlo = g_qlo + (size_t)bh * PBH;

    float acc = 0.f;
    const float* gq = g_gq + bh * 64 * Ec + e;
    for (int i = 0; i < gr; ++i) acc += gq[i * Ec];

    int j0 = g * 64 + r * 16;
    #pragma unroll
    for (int jj = 0; jj < 16; ++jj) {
        int j = j0 + jj;
        acc += g_wexp[bh * Lc + j] *
               q[((size_t)((b * Lc + j) * Hc + h)) * Ec + e];
        sbuf[r * 16 + jj][e] = acc * g_invz[bh * Lc + j];
    }
    __syncthreads();

    // phase 2: vectorized split + store
    #pragma unroll
    for (int itr = 0; itr < 4; ++itr) {
        int idx = itr * 256 + threadIdx.x;
        int lr = idx >> 4, c4 = idx & 15;
        float4 x = *(const float4*)&sbuf[lr][c4 * 4];
        unsigned h0, l0_, h1, l1;
        splitpack(x.x, x.y, h0, l0_);
        splitpack(x.z, x.w, h1, l1);
        unsigned off = swoff(g * 64 + lr, c4);
        *(uint2*)(qhi + off) = make_uint2(h0, h1);
        *(uint2*)(qlo + off) = make_uint2(l0_, l1);
    }
}

// ---------------------------------------------------------------------------
// 4) Stage 2: split-bf16 mma.sync flash attention. K double-buffered,
//    V single-buffered (issued at top, waited pre-PV). 3 CTAs/SM.
//    grid (NBH, NIT) heavy-first, 128 threads (4 warps x 16 rows)
// ---------------------------------------------------------------------------
__global__ void __launch_bounds__(128, 3) stage2_kernel(
    const float* __restrict__ q, const float* __restrict__ k_mask,
    float* __restrict__ out)
{
    extern __shared__ char smem[];
    const unsigned sbase = smem_u32(smem);
    int tid = threadIdx.x, lane = tid & 31, w = tid >> 5;
    int bh = blockIdx.x, b = bh / Hc, h = bh % Hc;
    int it = NIT - 1 - (int)blockIdx.y;   // heavy tiles first
    int i0 = it * BM;
    float twokm = 2.f * k_mask[b * Lc];
    const size_t bhoff = (size_t)bh * PBH;

    // ---- prologue: Q + K0 + V0 + kn0, one commit group ----
    {
        const unsigned char* sq_hi = g_qhi + bhoff + (size_t)i0 * 128;
        const unsigned char* sq_lo = g_qlo + bhoff + (size_t)i0 * 128;
        #pragma unroll
        for (int c = 0; c < 4; ++c) {
            unsigned off = (unsigned)((c * 128 + tid) * 16);
            cpa16(sbase + SQHI + off, sq_hi + off);
            cpa16(sbase + SQLO + off, sq_lo + off);
            cpa16(sbase + SKB + off,        g_khi + bhoff + off);
            cpa16(sbase + SKB + 8192 + off, g_klo + bhoff + off);
            cpa16(sbase + SVHI + off, g_vhi + bhoff + off);
            cpa16(sbase + SVLO + off, g_vlo + bhoff + off);
        }
        if (tid < BN)
            *(float*)(smem + SKNN + tid * 4) = g_kkn[bh * Lc + tid];
        asm volatile("cp.async.commit_group;");
    }

    // ---- per-lane fragment geometry ----
    int a_t = lane >> 3, a_r = lane & 7;
    int a_row = w * 16 + ((a_t & 1) << 3) + a_r;
    unsigned a_rowoff = (unsigned)(a_row * 128);
    unsigned a_x = (unsigned)((a_row & 7) << 4);
    unsigned a_cb = (unsigned)(((a_t >> 1) << 3) * 2);
    int b_half = (lane >> 3) & 1, b_r = lane & 7;
    unsigned b_cb = (unsigned)(b_half * 16);
    unsigned b_x = (unsigned)(b_r << 4);
    int rA = lane >> 2;
    int igA = i0 + w * 16 + rA, igB = igA + 8;
    int cA = (lane & 3) << 1;

    float oc[8][4];
    #pragma unroll
    for (int t = 0; t < 8; ++t)
        #pragma unroll
        for (int c = 0; c < 4; ++c) oc[t][c] = 0.f;
    float mA = -INFINITY, mB = -INFINITY, lA = 0.f, lB = 0.f;

    for (int jt = 0; jt <= it; ++jt) {
        int j0 = jt * BN;
        int buf = jt & 1;
        __syncthreads();   // all reads of V(jt-1), K(jt-1) buffer, kn(jt) staged

        // ---- issue V(jt) (jt>=1) and K(jt+1)+kn(jt+1) prefetches ----
        int nIss = 0;
        if (jt >= 1) {
            const size_t tg = bhoff + (size_t)j0 * 128;
            #pragma unroll
            for (int c = 0; c < 4; ++c) {
                unsigned off = (unsigned)((c * 128 + tid) * 16);
                cpa16(sbase + SVHI + off, g_vhi + tg + off);
                cpa16(sbase + SVLO + off, g_vlo + tg + off);
            }
            asm volatile("cp.async.commit_group;");
            ++nIss;
        }
        int kIss = 0;
        if (jt < it) {
            unsigned kb = SKB + (unsigned)(buf ^ 1) * 16384;
            const size_t tg = bhoff + (size_t)(j0 + BN) * 128;
            #pragma unroll
            for (int c = 0; c < 4; ++c) {
                unsigned off = (unsigned)((c * 128 + tid) * 16);
                cpa16(sbase + kb + off,        g_khi + tg + off);
                cpa16(sbase + kb + 8192 + off, g_klo + tg + off);
            }
            if (tid < BN)
                *(float*)(smem + SKNN + (buf ^ 1) * 256 + tid * 4) =
                    g_kkn[bh * Lc + j0 + BN + tid];
            asm volatile("cp.async.commit_group;");
            ++nIss; kIss = 1;
        }
        // wait: allow only the groups issued this iteration to be pending
        if (nIss == 2)      asm volatile("cp.async.wait_group 2;");
        else if (nIss == 1) asm volatile("cp.async.wait_group 1;");
        else                asm volatile("cp.async.wait_group 0;");
        __syncthreads();

        const char* knp = smem + SKNN + buf * 256;
        unsigned KHI = SKB + (unsigned)buf * 16384, KLO = KHI + 8192;

        // ---- S = Qhat . K^T  (3-split bf16) ----
        float sc_[8][4];
        #pragma unroll
        for (int t = 0; t < 8; ++t)
            #pragma unroll
            for (int c = 0; c < 4; ++c) sc_[t][c] = 0.f;

        #pragma unroll
        for (int ks = 0; ks < 4; ++ks) {
            unsigned ah[4], al[4];
            unsigned aoff = a_rowoff + (((unsigned)(ks * 32) + a_cb) ^ a_x);
            ldsm4(ah, sbase + SQHI + aoff);
            ldsm4(al, sbase + SQLO + aoff);
            #pragma unroll
            for (int t = 0; t < 8; ++t) {
                int jr = t * 8 + b_r;
                unsigned boff = (unsigned)(jr * 128) + (((unsigned)(ks * 32) + b_cb) ^ b_x);
                unsigned bh_[2], bl_[2];
                ldsm2(bh_, sbase + KHI + boff);
                ldsm2(bl_, sbase + KLO + boff);
                mma_bf16(sc_[t], ah, bh_);
                mma_bf16(sc_[t], ah, bl_);
                mma_bf16(sc_[t], al, bh_);
            }
        }

        // ---- scores + online softmax (quad lanes share row) ----
        float mxA = -INFINITY, mxB = -INFINITY;
        #pragma unroll
        for (int t = 0; t < 8; ++t) {
            int jb = j0 + t * 8 + cA;
            float k0 = *(const float*)(knp + (t * 8 + cA) * 4);
            float k1 = *(const float*)(knp + (t * 8 + cA + 1) * 4);
            float s0 = fmaf(twokm, sc_[t][0], k0); if (jb     > igA) s0 = -INFINITY;
            float s1 = fmaf(twokm, sc_[t][1], k1); if (jb + 1 > igA) s1 = -INFINITY;
            float s2 = fmaf(twokm, sc_[t][2], k0); if (jb     > igB) s2 = -INFINITY;
            float s3 = fmaf(twokm, sc_[t][3], k1); if (jb + 1 > igB) s3 = -INFINITY;
            sc_[t][0] = s0; sc_[t][1] = s1; sc_[t][2] = s2; sc_[t][3] = s3;
            mxA = fmaxf(mxA, fmaxf(s0, s1));
            mxB = fmaxf(mxB, fmaxf(s2, s3));
        }
        mxA = fmaxf(mxA, __shfl_xor_sync(0xffffffffu, mxA, 1));
        mxA = fmaxf(mxA, __shfl_xor_sync(0xffffffffu, mxA, 2));
        mxB = fmaxf(mxB, __shfl_xor_sync(0xffffffffu, mxB, 1));
        mxB = fmaxf(mxB, __shfl_xor_sync(0xffffffffu, mxB, 2));

        float mnA = fmaxf(mA, mxA), mnB = fmaxf(mB, mxB);
        float scA = __expf(mA - mnA), scB = __expf(mB - mnB);
        mA = mnA; mB = mnB;
        float rsA = 0.f, rsB = 0.f;
        #pragma unroll
        for (int t = 0; t < 8; ++t) {
            float p0 = __expf(sc_[t][0] - mnA);
            float p1 = __expf(sc_[t][1] - mnA);
            float p2 = __expf(sc_[t][2] - mnB);
            float p3 = __expf(sc_[t][3] - mnB);
            sc_[t][0] = p0; sc_[t][1] = p1; sc_[t][2] = p2; sc_[t][3] = p3;
            rsA += p0 + p1; rsB += p2 + p3;
        }
        rsA += __shfl_xor_sync(0xffffffffu, rsA, 1);
        rsA += __shfl_xor_sync(0xffffffffu, rsA, 2);
        rsB += __shfl_xor_sync(0xffffffffu, rsB, 1);
        rsB += __shfl_xor_sync(0xffffffffu, rsB, 2);
        lA = lA * scA + rsA;
        lB = lB * scB + rsB;
        #pragma unroll
        for (int t = 0; t < 8; ++t) {
            oc[t][0] *= scA; oc[t][1] *= scA;
            oc[t][2] *= scB; oc[t][3] *= scB;
        }

        // ---- wait V(jt) arrival, then O += P . V ----
        if (kIss) asm volatile("cp.async.wait_group 1;");
        else      asm volatile("cp.async.wait_group 0;");
        __syncthreads();

        #pragma unroll
        for (int ks = 0; ks < 4; ++ks) {
            unsigned pah[4], pal[4];
            splitpack(sc_[2 * ks][0],     sc_[2 * ks][1],     pah[0], pal[0]);
            splitpack(sc_[2 * ks][2],     sc_[2 * ks][3],     pah[1], pal[1]);
            splitpack(sc_[2 * ks + 1][0], sc_[2 * ks + 1][1], pah[2], pal[2]);
            splitpack(sc_[2 * ks + 1][2], sc_[2 * ks + 1][3], pah[3], pal[3]);
            int vr = ks * 16 + b_half * 8 + b_r;
            unsigned vbase = (unsigned)(vr * 128);
            #pragma unroll
            for (int t = 0; t < 8; ++t) {
                unsigned voff = vbase + (((unsigned)(t * 16)) ^ b_x);
                unsigned vh[2], vl[2];
                ldsm2t(vh, sbase + SVHI + voff);
                ldsm2t(vl, sbase + SVLO + voff);
                mma_bf16(oc[t], pah, vh);
                mma_bf16(oc[t], pah, vl);
                mma_bf16(oc[t], pal, vh);
            }
        }
    }

    // ---- epilogue: out = queries + O / l ----
    float liA = 1.f / lA, liB = 1.f / lB;
    #pragma unroll
    for (int t = 0; t < 8; ++t) {
        int e = t * 8 + cA;
        size_t offA = ((size_t)((b * Lc + igA) * Hc + h)) * Ec + e;
        size_t offB = ((size_t)((b * Lc + igB) * Hc + h)) * Ec + e;
        float2 qa = *(const float2*)(q + offA);
        float2 qb = *(const float2*)(q + offB);
        *(float2*)(out + offA) = make_float2(qa.x + oc[t][0] * liA,
                                             qa.y + oc[t][1] * liA);
        *(float2*)(out + offB) = make_float2(qb.x + oc[t][2] * liB,
                                             qb.y + oc[t][3] * liB);
    }
}

// ---------------------------------------------------------------------------

extern "C" void kernel_launch(void* const* d_in, const int* in_sizes, int n_in,
                              void* d_out, int out_size)
{
    const float* q  = (const float*)d_in[0];
    const float* k  = (const float*)d_in[1];
    const float* v  = (const float*)d_in[2];
    const float* qm = (const float*)d_in[3];
    const float* kmsk = (const float*)d_in[4];
    const float* w  = (const float*)d_in[5];
    float* out = (float*)d_out;

    cudaFuncSetAttribute(stage2_kernel,
                         cudaFuncAttributeMaxDynamicSharedMemorySize, STOT);

    prep_kernel<<<NBH + NBH * 4, 1024>>>(q, w, qm, k, v, kmsk);
    gsum_kernel<<<dim3(NBH, 16), 256>>>(q);
    qhat_kernel<<<dim3(NBH, 16), 256>>>(q);

    dim3 grid(NBH, NIT);   // y slow => heavy tiles (it = NIT-1-y) first
    stage2_kernel<<<grid, 128, STOT>>>(q, kmsk, out);
}